// round 12
// baseline (speedup 1.0000x reference)
#include <cuda_runtime.h>
#include <cuda_fp16.h>
#include <math.h>

#define NB   1024
#define NR   2336
#define NK   2
// Cin = 4, Cout = 16 (fixed)

__device__ float g_cls[NB * NK];

// ---------------------------------------------------------------------------
// Cluster-2 fused kernel. Cluster = 2 CTAs, same k, 4 batches total
// (rank 0: b0,b0+1; rank 1: b0+2,b0+3). Rank 0 multicasts W route-chunks
// (32 KB = 128 routes) into double-buffered smem of BOTH CTAs via
// cp.async.bulk.multicast::cluster. Projection reads W from smem (LDS),
// u from global (prefetched across the mbarrier wait).
// ---------------------------------------------------------------------------
#define RC          128
#define NCH         19              // 18 full chunks + tail (32 routes)
#define CHUNK_BYTES 32768
#define TAIL_ROUTES 32
#define TAIL_BYTES  8192

// smem layout (bytes)
#define PB_OFF      37440           // planeB offset inside a tile (==64 mod 128)
#define TILE_BYTES  74816
#define P0_OFF      0
#define P1_OFF      74816
#define BS0_OFF     149632          // fp16 logits, NR*2 = 4672 B
#define BS1_OFF     154304
#define RED0_OFF    158976          // 64 float4
#define RED1_OFF    160000
#define ZRED0_OFF   161024
#define ZRED1_OFF   161088
#define V0_OFF      161152
#define V1_OFF      161216
#define CLS0_OFF    161280
#define CLS1_OFF    161284
#define MBAR_OFF    161288          // full0,full1,empty0,empty1 (4 x 8 B)
#define WBUF_OFF    161792          // 1024-aligned, 2 x 32768
#define SMEM_BYTES  (WBUF_OFF + 2 * CHUNK_BYTES)   // 227328

// ---- PTX helpers ----------------------------------------------------------
__device__ __forceinline__ unsigned smem_u32(const void* p) {
    unsigned a;
    asm("{ .reg .u64 t; cvta.to.shared.u64 t, %1; cvt.u32.u64 %0, t; }"
        : "=r"(a) : "l"(p));
    return a;
}
__device__ __forceinline__ unsigned ctarank() {
    unsigned r; asm("mov.u32 %0, %%cluster_ctarank;" : "=r"(r)); return r;
}
#define MBAR_INIT(addr, cnt) \
    asm volatile("mbarrier.init.shared.b64 [%0], %1;" :: "r"(addr), "r"(cnt) : "memory")
#define MBAR_EXPECT(addr, bytes) \
    asm volatile("mbarrier.arrive.expect_tx.shared.b64 _, [%0], %1;" \
                 :: "r"(addr), "r"(bytes) : "memory")
#define MBAR_ARRIVE_RANK0(addr) \
    asm volatile("{\n\t.reg .b32 ra;\n\t" \
                 "mapa.shared::cluster.u32 ra, %0, 0;\n\t" \
                 "mbarrier.arrive.shared::cluster.b64 _, [ra];\n\t}" \
                 :: "r"(addr) : "memory")
#define MBAR_WAIT(addr, par) do { \
    unsigned _done; \
    asm volatile("{\n\t.reg .pred p;\n\t" \
        "mbarrier.try_wait.parity.acquire.cta.shared::cta.b64 p, [%1], %2;\n\t" \
        "selp.b32 %0, 1, 0, p;\n\t}" : "=r"(_done) : "r"(addr), "r"(par) : "memory"); \
    while (!_done) { \
        asm volatile("{\n\t.reg .pred p;\n\t" \
            "mbarrier.try_wait.parity.acquire.cta.shared::cta.b64 p, [%1], %2, 0x989680;\n\t" \
            "selp.b32 %0, 1, 0, p;\n\t}" : "=r"(_done) : "r"(addr), "r"(par) : "memory"); \
    } } while (0)
#define BULK_MCAST(dst, src, nbytes, mbar) \
    asm volatile("cp.async.bulk.shared::cluster.global" \
                 ".mbarrier::complete_tx::bytes.multicast::cluster" \
                 " [%0], [%1], %2, [%3], %4;" \
                 :: "r"(dst), "l"(src), "r"(nbytes), "r"(mbar), \
                    "h"((unsigned short)0x3) : "memory")
#define CLUSTER_SYNC() do { \
    asm volatile("barrier.cluster.arrive.aligned;" ::: "memory"); \
    asm volatile("barrier.cluster.wait.aligned;"  ::: "memory"); } while (0)

// ---------------------------------------------------------------------------
__device__ __forceinline__ void squash_store(const float4* red, float4* v4s,
                                             float* clsp, float cn)
{
    float s[16];
#pragma unroll
    for (int qq = 0; qq < 4; qq++) {
        float4 a = red[qq];
        s[qq*4+0] = a.x * cn; s[qq*4+1] = a.y * cn;
        s[qq*4+2] = a.z * cn; s[qq*4+3] = a.w * cn;
    }
    float n = 0.f;
#pragma unroll
    for (int o = 0; o < 16; o++) n += s[o] * s[o];
    float f = n / ((1.f + n) * sqrtf(fmaxf(n, 1e-30f)));
#pragma unroll
    for (int qq = 0; qq < 4; qq++)
        v4s[qq] = make_float4(f*s[qq*4+0], f*s[qq*4+1], f*s[qq*4+2], f*s[qq*4+3]);
    *clsp = n / (1.f + n);
}

#define XOR_RED4(a, off) do { \
    a.x += __shfl_xor_sync(0xffffffffu, a.x, off); \
    a.y += __shfl_xor_sync(0xffffffffu, a.y, off); \
    a.z += __shfl_xor_sync(0xffffffffu, a.z, off); \
    a.w += __shfl_xor_sync(0xffffffffu, a.w, off); } while (0)

#define H2F2(dst, i, hw) do { \
    float2 _f = __half22float2(*reinterpret_cast<const __half2*>(&(hw))); \
    dst[i] = _f.x; dst[(i)+1] = _f.y; } while (0)

__global__ void __launch_bounds__(512, 1) __cluster_dims__(2, 1, 1)
caps_fused_kernel(
    const float4* __restrict__ u4,   // u: [b*NR + r] float4
    const char*   __restrict__ Wg)   // W: [(k*NR+r)*256 B]
{
    extern __shared__ char smb[];
    const unsigned sbase = smem_u32(smb);
    const int t = threadIdx.x;
    const int lane = t & 31, warp = t >> 5;
    const unsigned rank = ctarank();
    const int cluster_id = blockIdx.x >> 1;
    const int k  = cluster_id & 1;
    const int b0 = (cluster_id >> 1) * 4 + (int)rank * 2;

    const float4* ub0 = u4 + (size_t)b0 * NR;
    const float4* ub1 = ub0 + NR;
    const char*   Wk  = Wg + (size_t)k * NR * 256;

    float4* red0  = (float4*)(smb + RED0_OFF);
    float4* red1  = (float4*)(smb + RED1_OFF);
    float*  zred0 = (float*)(smb + ZRED0_OFF);
    float*  zred1 = (float*)(smb + ZRED1_OFF);
    float4* v4s0  = (float4*)(smb + V0_OFF);
    float4* v4s1  = (float4*)(smb + V1_OFF);

    const unsigned mb_full0  = sbase + MBAR_OFF;
    const unsigned mb_full1  = sbase + MBAR_OFF + 8;
    const unsigned mb_empty0 = sbase + MBAR_OFF + 16;
    const unsigned mb_empty1 = sbase + MBAR_OFF + 24;

    // --- init barriers + pre-expect chunks 0,1 ---
    if (t == 0) {
        MBAR_INIT(mb_full0, 1);  MBAR_INIT(mb_full1, 1);
        MBAR_INIT(mb_empty0, 2); MBAR_INIT(mb_empty1, 2);
        MBAR_EXPECT(mb_full0, CHUNK_BYTES);
        MBAR_EXPECT(mb_full1, CHUNK_BYTES);
    }
    __syncthreads();
    CLUSTER_SYNC();
    if (rank == 0 && t == 0) {
        BULK_MCAST(sbase + WBUF_OFF,               Wk,                        CHUNK_BYTES, mb_full0);
        BULK_MCAST(sbase + WBUF_OFF + CHUNK_BYTES, Wk + (size_t)CHUNK_BYTES,  CHUNK_BYTES, mb_full1);
    }

    // --- Phase 1: chunked projection -> fp16 planes, fused uniform-c sweep ---
    const int q = t & 3;                 // out-quad
    const int g = t >> 2;                // route-in-chunk 0..127
    const int rot = g & 1;
    const int of0 = rot * 64;
    const int of1 = ( 64 + rot * 64) & 255;
    const int of2 = (128 + rot * 64) & 255;
    const int of3 = (192 + rot * 64) & 255;
    const char* wrow = smb + WBUF_OFF + g * 256 + q * 16;

    uint2* dst0 = (uint2*)(smb + P0_OFF + (q < 2 ? 0 : PB_OFF)) + (q & 1);
    uint2* dst1 = (uint2*)(smb + P1_OFF + (q < 2 ? 0 : PB_OFF)) + (q & 1);

    float4 acc0 = make_float4(0.f,0.f,0.f,0.f);
    float4 acc1 = make_float4(0.f,0.f,0.f,0.f);

    for (int c = 0; c < NCH; c++) {
        const int buf = c & 1;
        const int par = (c >> 1) & 1;
        const int nrt = (c == NCH-1) ? TAIL_ROUTES : RC;
        const bool act = g < nrt;
        const int r = c * RC + g;

        float4 uu0, uu1;
        if (act) { uu0 = __ldg(ub0 + r); uu1 = __ldg(ub1 + r); }  // hides behind wait

        MBAR_WAIT(buf ? mb_full1 : mb_full0, par);

        if (act) {
            const char* wr = wrow + buf * CHUNK_BYTES;
            float4 w0 = *(const float4*)(wr + of0);
            float4 w1 = *(const float4*)(wr + of1);
            float4 w2 = *(const float4*)(wr + of2);
            float4 w3 = *(const float4*)(wr + of3);
            // u components permuted to match rotated W groups
            float a0 = rot ? uu0.y : uu0.x,  a1 = rot ? uu0.z : uu0.y;
            float a2 = rot ? uu0.w : uu0.z,  a3 = rot ? uu0.x : uu0.w;
            float c0 = rot ? uu1.y : uu1.x,  c1 = rot ? uu1.z : uu1.y;
            float c2 = rot ? uu1.w : uu1.z,  c3 = rot ? uu1.x : uu1.w;
            float4 o0, o1;
            o0.x = fmaf(a0,w0.x, fmaf(a1,w1.x, fmaf(a2,w2.x, a3*w3.x)));
            o0.y = fmaf(a0,w0.y, fmaf(a1,w1.y, fmaf(a2,w2.y, a3*w3.y)));
            o0.z = fmaf(a0,w0.z, fmaf(a1,w1.z, fmaf(a2,w2.z, a3*w3.z)));
            o0.w = fmaf(a0,w0.w, fmaf(a1,w1.w, fmaf(a2,w2.w, a3*w3.w)));
            o1.x = fmaf(c0,w0.x, fmaf(c1,w1.x, fmaf(c2,w2.x, c3*w3.x)));
            o1.y = fmaf(c0,w0.y, fmaf(c1,w1.y, fmaf(c2,w2.y, c3*w3.y)));
            o1.z = fmaf(c0,w0.z, fmaf(c1,w1.z, fmaf(c2,w2.z, c3*w3.z)));
            o1.w = fmaf(c0,w0.w, fmaf(c1,w1.w, fmaf(c2,w2.w, c3*w3.w)));
            acc0.x += o0.x; acc0.y += o0.y; acc0.z += o0.z; acc0.w += o0.w;
            acc1.x += o1.x; acc1.y += o1.y; acc1.z += o1.z; acc1.w += o1.w;
            __half2 hA0 = __floats2half2_rn(o0.x, o0.y);
            __half2 hB0 = __floats2half2_rn(o0.z, o0.w);
            __half2 hA1 = __floats2half2_rn(o1.x, o1.y);
            __half2 hB1 = __floats2half2_rn(o1.z, o1.w);
            uint2 hv0, hv1;
            hv0.x = *reinterpret_cast<unsigned*>(&hA0);
            hv0.y = *reinterpret_cast<unsigned*>(&hB0);
            hv1.x = *reinterpret_cast<unsigned*>(&hA1);
            hv1.y = *reinterpret_cast<unsigned*>(&hB1);
            dst0[(size_t)r * 2] = hv0;
            dst1[(size_t)r * 2] = hv1;
        }
        __syncthreads();                 // all reads of buf done
        if (t == 0 && c + 2 < NCH) {
            MBAR_EXPECT(buf ? mb_full1 : mb_full0,
                        (c + 2 == NCH-1) ? TAIL_BYTES : CHUNK_BYTES);
            MBAR_ARRIVE_RANK0(buf ? mb_empty1 : mb_empty0);
        }
        if (rank == 0 && t == 0 && c + 2 < NCH) {
            MBAR_WAIT(buf ? mb_empty1 : mb_empty0, par);
            int nb = (c + 2 == NCH-1) ? TAIL_BYTES : CHUNK_BYTES;
            BULK_MCAST(sbase + WBUF_OFF + buf * CHUNK_BYTES,
                       Wk + (size_t)(c + 2) * CHUNK_BYTES, nb,
                       buf ? mb_full1 : mb_full0);
        }
    }

    // reduce acc across threads sharing q
    XOR_RED4(acc0, 4); XOR_RED4(acc0, 8); XOR_RED4(acc0, 16);
    XOR_RED4(acc1, 4); XOR_RED4(acc1, 8); XOR_RED4(acc1, 16);
    if (lane < 4) { red0[warp*4 + lane] = acc0; red1[warp*4 + lane] = acc1; }
    __syncthreads();
    if (warp < 2) {
        float4* rg = warp ? red1 : red0;
        float4 a = rg[lane], bx = rg[lane + 32];
        a.x += bx.x; a.y += bx.y; a.z += bx.z; a.w += bx.w;
        XOR_RED4(a, 4); XOR_RED4(a, 8); XOR_RED4(a, 16);
        if (lane < 4) rg[lane] = a;
        __syncwarp();
        if (lane == 0)
            squash_store(rg, warp ? v4s1 : v4s0,
                         (float*)(smb + (warp ? CLS1_OFF : CLS0_OFF)),
                         1.f / (float)NR);
    }
    __syncthreads();

    // --- Phase 2: two fused (b-update + softmax s-sweep) iterations ---
    const int grp = warp >> 3;                 // 0: batch b0, 1: batch b0+1
    const int tt  = t & 255;
    const uint4* pA = (const uint4*)(smb + (grp ? P1_OFF : P0_OFF));
    const uint4* pB = (const uint4*)(smb + (grp ? P1_OFF : P0_OFF) + PB_OFF);
    __half* bs    = (__half*)(smb + (grp ? BS1_OFF : BS0_OFF));
    float4* redg  = grp ? red1 : red0;
    float*  zredg = grp ? zred1 : zred0;
    float4* v4sg  = grp ? v4s1 : v4s0;

#pragma unroll
    for (int it = 0; it < 2; it++) {
        float vv[16];
        {
            float4 t0 = v4sg[0], t1 = v4sg[1], t2 = v4sg[2], t3 = v4sg[3];
            vv[0]=t0.x; vv[1]=t0.y; vv[2]=t0.z; vv[3]=t0.w;
            vv[4]=t1.x; vv[5]=t1.y; vv[6]=t1.z; vv[7]=t1.w;
            vv[8]=t2.x; vv[9]=t2.y; vv[10]=t2.z; vv[11]=t2.w;
            vv[12]=t3.x; vv[13]=t3.y; vv[14]=t3.z; vv[15]=t3.w;
        }
        float a[16];
#pragma unroll
        for (int o = 0; o < 16; o++) a[o] = 0.f;
        float Z = 0.f;

#pragma unroll 2
        for (int r = tt; r < NR; r += 256) {
            uint4 ha = pA[r];
            uint4 hb = pB[r];
            float x[16];
            H2F2(x, 0,  ha.x); H2F2(x, 2,  ha.y);
            H2F2(x, 4,  ha.z); H2F2(x, 6,  ha.w);
            H2F2(x, 8,  hb.x); H2F2(x, 10, hb.y);
            H2F2(x, 12, hb.z); H2F2(x, 14, hb.w);
            float d = x[0] * vv[0];
#pragma unroll
            for (int o = 1; o < 16; o++) d = fmaf(x[o], vv[o], d);
            float bn;
            if (it == 0) { bn = d; bs[r] = __float2half_rn(d); }
            else         { bn = __half2float(bs[r]) + d; }
            float e = __expf(bn);
            Z += e;
#pragma unroll
            for (int o = 0; o < 16; o++) a[o] = fmaf(e, x[o], a[o]);
        }

#pragma unroll
        for (int off = 1; off < 32; off <<= 1) {
#pragma unroll
            for (int o = 0; o < 16; o++)
                a[o] += __shfl_xor_sync(0xffffffffu, a[o], off);
            Z += __shfl_xor_sync(0xffffffffu, Z, off);
        }
        if (lane == 0) {
            int w = warp & 7;
            redg[w*4+0] = make_float4(a[0],  a[1],  a[2],  a[3]);
            redg[w*4+1] = make_float4(a[4],  a[5],  a[6],  a[7]);
            redg[w*4+2] = make_float4(a[8],  a[9],  a[10], a[11]);
            redg[w*4+3] = make_float4(a[12], a[13], a[14], a[15]);
            zredg[w] = Z;
        }
        __syncthreads();
        if (warp < 2) {
            float4* rg = warp ? red1 : red0;
            float*  zg = warp ? zred1 : zred0;
            float4 c4 = rg[lane];
            XOR_RED4(c4, 4); XOR_RED4(c4, 8); XOR_RED4(c4, 16);
            float Zt = (lane < 8) ? zg[lane] : 0.f;
            Zt += __shfl_xor_sync(0xffffffffu, Zt, 1);
            Zt += __shfl_xor_sync(0xffffffffu, Zt, 2);
            Zt += __shfl_xor_sync(0xffffffffu, Zt, 4);
            if (lane < 4) rg[lane] = c4;
            __syncwarp();
            if (lane == 0)
                squash_store(rg, warp ? v4s1 : v4s0,
                             (float*)(smb + (warp ? CLS1_OFF : CLS0_OFF)),
                             1.f / Zt);
        }
        __syncthreads();
    }

    if (t == 0) {
        g_cls[(size_t)b0 * 2 + k]       = *(float*)(smb + CLS0_OFF);
        g_cls[(size_t)(b0 + 1) * 2 + k] = *(float*)(smb + CLS1_OFF);
    }
    CLUSTER_SYNC();   // no CTA exits while peer smem ops may be in flight
}

// ---------------------------------------------------------------------------
__global__ void caps_softmax_kernel(float* __restrict__ out)
{
    int b = blockIdx.x * blockDim.x + threadIdx.x;
    if (b < NB) {
        float c0 = g_cls[2*b], c1 = g_cls[2*b + 1];
        float m  = fmaxf(c0, c1);
        float e0 = expf(c0 - m), e1 = expf(c1 - m);
        float inv = 1.f / (e0 + e1);
        out[2*b]     = e0 * inv;
        out[2*b + 1] = e1 * inv;
    }
}

// ---------------------------------------------------------------------------
extern "C" void kernel_launch(void* const* d_in, const int* in_sizes, int n_in,
                              void* d_out, int out_size)
{
    const float4* u4 = (const float4*)d_in[0];   // u: [1024,2336,4] f32
    const char*   Wg = (const char*)d_in[1];     // W: [2,2336,4,16] f32
    (void)in_sizes; (void)n_in; (void)out_size;

    cudaFuncSetAttribute(caps_fused_kernel,
                         cudaFuncAttributeMaxDynamicSharedMemorySize, SMEM_BYTES);

    caps_fused_kernel<<<NB, 512, SMEM_BYTES>>>(u4, Wg);
    caps_softmax_kernel<<<(NB + 255) / 256, 256>>>((float*)d_out);
}

// round 13
// speedup vs baseline: 1.4520x; 1.4520x over previous
#include <cuda_runtime.h>
#include <cuda_fp16.h>
#include <math.h>

#define NB   1024
#define NR   2336
#define NK   2
// Cin = 4, Cout = 16 (fixed)

__device__ float g_cls[NB * NK];
// Pre-converted fp16 W: per (k,r,q): 16 halfs (i=0..3 x out-in-quad 0..3) = 32 B
// index: ((k*NR + r)*4 + q) * 2 uint4
__device__ uint4 g_W16[(size_t)NK * NR * 4 * 2];

// ---------------------------------------------------------------------------
// W conversion kernel: f32 -> packed fp16, quad-contiguous layout.
// ---------------------------------------------------------------------------
__global__ void conv_w_kernel(const float4* __restrict__ W4)
{
    int idx = blockIdx.x * blockDim.x + threadIdx.x;   // (k*NR+r)*4 + q
    if (idx < NK * NR * 4) {
        int q  = idx & 3;
        int kr = idx >> 2;
        const float4* wp = W4 + (size_t)kr * 16 + q;
        float4 w0 = __ldg(wp);      float4 w1 = __ldg(wp + 4);
        float4 w2 = __ldg(wp + 8);  float4 w3 = __ldg(wp + 12);
        __half2 h0 = __floats2half2_rn(w0.x, w0.y), h1 = __floats2half2_rn(w0.z, w0.w);
        __half2 h2 = __floats2half2_rn(w1.x, w1.y), h3 = __floats2half2_rn(w1.z, w1.w);
        __half2 h4 = __floats2half2_rn(w2.x, w2.y), h5 = __floats2half2_rn(w2.z, w2.w);
        __half2 h6 = __floats2half2_rn(w3.x, w3.y), h7 = __floats2half2_rn(w3.z, w3.w);
        uint4 p0, p1;
        p0.x = *(unsigned*)&h0; p0.y = *(unsigned*)&h1;
        p0.z = *(unsigned*)&h2; p0.w = *(unsigned*)&h3;
        p1.x = *(unsigned*)&h4; p1.y = *(unsigned*)&h5;
        p1.z = *(unsigned*)&h6; p1.w = *(unsigned*)&h7;
        g_W16[(size_t)idx * 2]     = p0;
        g_W16[(size_t)idx * 2 + 1] = p1;
    }
}

// ---------------------------------------------------------------------------
// Fused kernel: projection + routing, TWO batches per CTA (same k).
// u_ji tiles in smem as fp16 half-planes (see R9 layout notes):
//   per batch: planeA (quads 0-1, 16 B/route) | 64 B pad | planeB (quads 2-3)
//   A->B offset == 64 (mod 128) => stores and per-route LDS.128 conflict-free.
// ---------------------------------------------------------------------------
#define PB_OFF      37440
#define TILE_BYTES  74816
#define P0_OFF      0
#define P1_OFF      TILE_BYTES
#define BS0_OFF     (2*TILE_BYTES)          // fp32 logits b[r], batch 0
#define BS1_OFF     (BS0_OFF + NR*4)
#define RED0_OFF    (BS1_OFF + NR*4)        // 64 float4
#define RED1_OFF    (RED0_OFF + 1024)
#define ZRED0_OFF   (RED1_OFF + 1024)
#define ZRED1_OFF   (ZRED0_OFF + 64)
#define V0_OFF      (ZRED1_OFF + 64)
#define V1_OFF      (V0_OFF + 64)
#define CLS0_OFF    (V1_OFF + 64)
#define CLS1_OFF    (CLS0_OFF + 4)
#define SMEM_BYTES  (CLS1_OFF + 12)         // ~170.6 KB -> 1 CTA/SM

__device__ __forceinline__ void squash_store(const float4* red, float4* v4s,
                                             float* clsp, float cn)
{
    float s[16];
#pragma unroll
    for (int qq = 0; qq < 4; qq++) {
        float4 a = red[qq];
        s[qq*4+0] = a.x * cn; s[qq*4+1] = a.y * cn;
        s[qq*4+2] = a.z * cn; s[qq*4+3] = a.w * cn;
    }
    float n = 0.f;
#pragma unroll
    for (int o = 0; o < 16; o++) n += s[o] * s[o];
    // squash: v = (n/(1+n)) * s / sqrt(n);  |v| = n/(1+n)
    float f = n / ((1.f + n) * sqrtf(fmaxf(n, 1e-30f)));
#pragma unroll
    for (int qq = 0; qq < 4; qq++)
        v4s[qq] = make_float4(f*s[qq*4+0], f*s[qq*4+1], f*s[qq*4+2], f*s[qq*4+3]);
    *clsp = n / (1.f + n);
}

#define XOR_RED4(a, off) do { \
    a.x += __shfl_xor_sync(0xffffffffu, a.x, off); \
    a.y += __shfl_xor_sync(0xffffffffu, a.y, off); \
    a.z += __shfl_xor_sync(0xffffffffu, a.z, off); \
    a.w += __shfl_xor_sync(0xffffffffu, a.w, off); } while (0)

#define H2F2(dst, i, hw) do { \
    float2 _f = __half22float2(*reinterpret_cast<const __half2*>(&(hw))); \
    dst[i] = _f.x; dst[(i)+1] = _f.y; } while (0)

// Phase-1 body: thread (g = route-in-chunk, q = out-quad) computes one quad
// for BOTH batches. W read as packed fp16 (32 B), u as f32.
#define PROJ2(r) do { \
    const uint4* wp = w16 + (size_t)(r) * 8 + q * 2; \
    uint4 hw0 = __ldg(wp); uint4 hw1 = __ldg(wp + 1); \
    float4 uu0 = __ldg(&ub0[(r)]); \
    float4 uu1 = __ldg(&ub1[(r)]); \
    float w[16]; \
    H2F2(w, 0,  hw0.x); H2F2(w, 2,  hw0.y); \
    H2F2(w, 4,  hw0.z); H2F2(w, 6,  hw0.w); \
    H2F2(w, 8,  hw1.x); H2F2(w, 10, hw1.y); \
    H2F2(w, 12, hw1.z); H2F2(w, 14, hw1.w); \
    float4 o0, o1; \
    o0.x = fmaf(uu0.x,w[0], fmaf(uu0.y,w[4], fmaf(uu0.z,w[8],  uu0.w*w[12]))); \
    o0.y = fmaf(uu0.x,w[1], fmaf(uu0.y,w[5], fmaf(uu0.z,w[9],  uu0.w*w[13]))); \
    o0.z = fmaf(uu0.x,w[2], fmaf(uu0.y,w[6], fmaf(uu0.z,w[10], uu0.w*w[14]))); \
    o0.w = fmaf(uu0.x,w[3], fmaf(uu0.y,w[7], fmaf(uu0.z,w[11], uu0.w*w[15]))); \
    o1.x = fmaf(uu1.x,w[0], fmaf(uu1.y,w[4], fmaf(uu1.z,w[8],  uu1.w*w[12]))); \
    o1.y = fmaf(uu1.x,w[1], fmaf(uu1.y,w[5], fmaf(uu1.z,w[9],  uu1.w*w[13]))); \
    o1.z = fmaf(uu1.x,w[2], fmaf(uu1.y,w[6], fmaf(uu1.z,w[10], uu1.w*w[14]))); \
    o1.w = fmaf(uu1.x,w[3], fmaf(uu1.y,w[7], fmaf(uu1.z,w[11], uu1.w*w[15]))); \
    acc0.x += o0.x; acc0.y += o0.y; acc0.z += o0.z; acc0.w += o0.w; \
    acc1.x += o1.x; acc1.y += o1.y; acc1.z += o1.z; acc1.w += o1.w; \
    __half2 hA0 = __floats2half2_rn(o0.x, o0.y); \
    __half2 hB0 = __floats2half2_rn(o0.z, o0.w); \
    __half2 hA1 = __floats2half2_rn(o1.x, o1.y); \
    __half2 hB1 = __floats2half2_rn(o1.z, o1.w); \
    uint2 hv0, hv1; \
    hv0.x = *reinterpret_cast<unsigned*>(&hA0); \
    hv0.y = *reinterpret_cast<unsigned*>(&hB0); \
    hv1.x = *reinterpret_cast<unsigned*>(&hA1); \
    hv1.y = *reinterpret_cast<unsigned*>(&hB1); \
    dst0[(size_t)(r) * 2] = hv0; \
    dst1[(size_t)(r) * 2] = hv1; } while (0)

__global__ void __launch_bounds__(512, 1) caps_fused_kernel(
    const float4* __restrict__ u4)   // u as float4: [b*NR + r]
{
    extern __shared__ char smb[];
    const int t = threadIdx.x;
    const int lane = t & 31, warp = t >> 5;
    const int cid = blockIdx.x;
    const int k  = cid & 1;
    const int b0 = (cid >> 1) * 2;           // batches b0, b0+1

    const float4* ub0 = u4 + (size_t)b0 * NR;
    const float4* ub1 = ub0 + NR;
    const uint4*  w16 = g_W16 + (size_t)k * NR * 8;

    float4* red0  = (float4*)(smb + RED0_OFF);
    float4* red1  = (float4*)(smb + RED1_OFF);
    float*  zred0 = (float*)(smb + ZRED0_OFF);
    float*  zred1 = (float*)(smb + ZRED1_OFF);
    float4* v4s0  = (float4*)(smb + V0_OFF);
    float4* v4s1  = (float4*)(smb + V1_OFF);

    // --- Phase 1: projection -> fp16 planes, fused sweep-1 (uniform c) ---
    const int q = t & 3;                     // out-quad
    const int g = t >> 2;                    // route-in-chunk 0..127
    uint2* dst0 = (uint2*)(smb + P0_OFF + (q < 2 ? 0 : PB_OFF)) + (q & 1);
    uint2* dst1 = (uint2*)(smb + P1_OFF + (q < 2 ? 0 : PB_OFF)) + (q & 1);

    float4 acc0 = make_float4(0.f,0.f,0.f,0.f);
    float4 acc1 = make_float4(0.f,0.f,0.f,0.f);
#pragma unroll 2
    for (int c = 0; c < 18; c++) {           // 18*128 = 2304 routes
        int r = c * 128 + g;
        PROJ2(r);
    }
    if (g < 32) {                            // tail: routes 2304..2335
        int r = 2304 + g;
        PROJ2(r);
    }

    // reduce acc across threads sharing q (8 per warp, 16 warps)
    XOR_RED4(acc0, 4); XOR_RED4(acc0, 8); XOR_RED4(acc0, 16);
    XOR_RED4(acc1, 4); XOR_RED4(acc1, 8); XOR_RED4(acc1, 16);
    if (lane < 4) { red0[warp*4 + lane] = acc0; red1[warp*4 + lane] = acc1; }
    __syncthreads();
    if (warp < 2) {
        float4* rg = warp ? red1 : red0;
        float4 a = rg[lane], bx = rg[lane + 32];
        a.x += bx.x; a.y += bx.y; a.z += bx.z; a.w += bx.w;
        XOR_RED4(a, 4); XOR_RED4(a, 8); XOR_RED4(a, 16);
        if (lane < 4) rg[lane] = a;
        __syncwarp();
        if (lane == 0)
            squash_store(rg, warp ? v4s1 : v4s0,
                         (float*)(smb + (warp ? CLS1_OFF : CLS0_OFF)),
                         1.f / (float)NR);
    }
    __syncthreads();

    // --- Phase 2: two fused (b-update + softmax s-sweep) iterations ---
    // warps 0-7 -> batch 0, warps 8-15 -> batch 1; thread-per-route.
    const int grp = warp >> 3;
    const int tt  = t & 255;
    const uint4* pA = (const uint4*)(smb + (grp ? P1_OFF : P0_OFF));
    const uint4* pB = (const uint4*)(smb + (grp ? P1_OFF : P0_OFF) + PB_OFF);
    float* bs     = (float*)(smb + (grp ? BS1_OFF : BS0_OFF));
    float4* redg  = grp ? red1 : red0;
    float*  zredg = grp ? zred1 : zred0;
    float4* v4sg  = grp ? v4s1 : v4s0;

#pragma unroll
    for (int it = 0; it < 2; it++) {
        float vv[16];
        {
            float4 t0 = v4sg[0], t1 = v4sg[1], t2 = v4sg[2], t3 = v4sg[3];
            vv[0]=t0.x; vv[1]=t0.y; vv[2]=t0.z; vv[3]=t0.w;
            vv[4]=t1.x; vv[5]=t1.y; vv[6]=t1.z; vv[7]=t1.w;
            vv[8]=t2.x; vv[9]=t2.y; vv[10]=t2.z; vv[11]=t2.w;
            vv[12]=t3.x; vv[13]=t3.y; vv[14]=t3.z; vv[15]=t3.w;
        }
        float a[16];
#pragma unroll
        for (int o = 0; o < 16; o++) a[o] = 0.f;
        float Z = 0.f;

#pragma unroll 2
        for (int r = tt; r < NR; r += 256) {
            uint4 ha = pA[r];                // quads 0-1 (8 halfs)
            uint4 hb = pB[r];                // quads 2-3
            float x[16];
            H2F2(x, 0,  ha.x); H2F2(x, 2,  ha.y);
            H2F2(x, 4,  ha.z); H2F2(x, 6,  ha.w);
            H2F2(x, 8,  hb.x); H2F2(x, 10, hb.y);
            H2F2(x, 12, hb.z); H2F2(x, 14, hb.w);
            float d = x[0] * vv[0];
#pragma unroll
            for (int o = 1; o < 16; o++) d = fmaf(x[o], vv[o], d);
            float bn;
            if (it == 0) { bn = d; bs[r] = d; }
            else         { bn = bs[r] + d; }
            float e = __expf(bn);            // logits bounded, no max-shift
            Z += e;
#pragma unroll
            for (int o = 0; o < 16; o++) a[o] = fmaf(e, x[o], a[o]);
        }

        // intra-warp reduce
#pragma unroll
        for (int off = 1; off < 32; off <<= 1) {
#pragma unroll
            for (int o = 0; o < 16; o++)
                a[o] += __shfl_xor_sync(0xffffffffu, a[o], off);
            Z += __shfl_xor_sync(0xffffffffu, Z, off);
        }
        if (lane == 0) {
            int w = warp & 7;
            redg[w*4+0] = make_float4(a[0],  a[1],  a[2],  a[3]);
            redg[w*4+1] = make_float4(a[4],  a[5],  a[6],  a[7]);
            redg[w*4+2] = make_float4(a[8],  a[9],  a[10], a[11]);
            redg[w*4+3] = make_float4(a[12], a[13], a[14], a[15]);
            zredg[w] = Z;
        }
        __syncthreads();
        if (warp < 2) {                      // warp0 -> batch0, warp1 -> batch1
            float4* rg = warp ? red1 : red0;
            float*  zg = warp ? zred1 : zred0;
            float4 c4 = rg[lane];            // 32 entries: (w 0..7) x (q 0..3)
            XOR_RED4(c4, 4); XOR_RED4(c4, 8); XOR_RED4(c4, 16);
            float Zt = (lane < 8) ? zg[lane] : 0.f;
            Zt += __shfl_xor_sync(0xffffffffu, Zt, 1);
            Zt += __shfl_xor_sync(0xffffffffu, Zt, 2);
            Zt += __shfl_xor_sync(0xffffffffu, Zt, 4);
            if (lane < 4) rg[lane] = c4;
            __syncwarp();
            if (lane == 0)
                squash_store(rg, warp ? v4s1 : v4s0,
                             (float*)(smb + (warp ? CLS1_OFF : CLS0_OFF)),
                             1.f / Zt);
        }
        __syncthreads();
    }

    if (t == 0) {
        g_cls[(size_t)b0 * 2 + k]       = *(float*)(smb + CLS0_OFF);
        g_cls[(size_t)(b0 + 1) * 2 + k] = *(float*)(smb + CLS1_OFF);
    }
}

// ---------------------------------------------------------------------------
// Final softmax over K=2 classes per batch
// ---------------------------------------------------------------------------
__global__ void caps_softmax_kernel(float* __restrict__ out)
{
    int b = blockIdx.x * blockDim.x + threadIdx.x;
    if (b < NB) {
        float c0 = g_cls[2*b], c1 = g_cls[2*b + 1];
        float m  = fmaxf(c0, c1);
        float e0 = expf(c0 - m), e1 = expf(c1 - m);
        float inv = 1.f / (e0 + e1);
        out[2*b]     = e0 * inv;
        out[2*b + 1] = e1 * inv;
    }
}

// ---------------------------------------------------------------------------
extern "C" void kernel_launch(void* const* d_in, const int* in_sizes, int n_in,
                              void* d_out, int out_size)
{
    const float4* u4 = (const float4*)d_in[0];   // u: [1024,2336,4] f32
    const float4* W4 = (const float4*)d_in[1];   // W: [2,2336,4,16] f32
    (void)in_sizes; (void)n_in; (void)out_size;

    cudaFuncSetAttribute(caps_fused_kernel,
                         cudaFuncAttributeMaxDynamicSharedMemorySize, SMEM_BYTES);

    conv_w_kernel<<<(NK * NR * 4 + 255) / 256, 256>>>(W4);
    caps_fused_kernel<<<NB, 512, SMEM_BYTES>>>(u4);
    caps_softmax_kernel<<<(NB + 255) / 256, 256>>>((float*)d_out);
}